// round 16
// baseline (speedup 1.0000x reference)
#include <cuda_runtime.h>
#include <cuda_bf16.h>
#include <cstdint>

#define NN 16384
#define MM 2048
#define DD 256

// 64-row n-tiles, 256 CTAs, 2 CTAs/SM, 256 threads. CTA m-chunk tile 64x256.
// B streams via per-warp private cp.async rings (4 stages x 2KB/warp).
// dynamic SMEM layout (bytes)
#define SM_A     0                 // A': 2048 uint4 (bf16) = 32768
#define SM_B     32768             // 8 warps x 4 stages x 2KB = 65536
#define SM_ZPART 98304             // 256 f32
#define SM_ZROW  99328             // 64 f32
#define SMEM_TOTAL 99584

// g_eB layout (1MB): uint2 at gid = g*1024 + wx*256 + nfp*64 + ln*2 + h
// byte addr: g*8192 + wx*2048 + nfp*512 + ln*16 + h*8  (64B contiguous per (wx,ln))
__device__ __align__(16) uint2 g_eB[DD * MM / 4];
__device__ float    g_esq[MM];
__device__ unsigned g_colmin[MM];

// ---------------------------------------------------------------------------
__device__ __forceinline__ uint32_t bf2(float lo, float hi) {
    uint32_t r;
    asm("cvt.rn.bf16x2.f32 %0, %1, %2;" : "=r"(r) : "f"(hi), "f"(lo));
    return r;
}
__device__ __forceinline__ uint32_t smem_u32(const void* p) {
    uint32_t a;
    asm("{ .reg .u64 t; cvta.to.shared.u64 t, %1; cvt.u32.u64 %0, t; }" : "=r"(a) : "l"(p));
    return a;
}
#define CP_ASYNC16(dst, src) \
    asm volatile("cp.async.cg.shared.global [%0], [%1], 16;" :: "r"(dst), "l"(src))
#define CP_COMMIT() asm volatile("cp.async.commit_group;" ::: "memory")
#define CP_WAIT(n)  asm volatile("cp.async.wait_group %0;" :: "n"(n) : "memory")
#define RED_MIN_U32(ptr, val) \
    asm volatile("red.global.min.u32 [%0], %1;" :: "l"(ptr), "r"(val) : "memory")

__device__ __forceinline__ void mma_bf16(float4& d, const uint4& a, uint32_t b0, uint32_t b1) {
    asm volatile("mma.sync.aligned.m16n8k16.row.col.f32.bf16.bf16.f32 "
        "{%0,%1,%2,%3}, {%4,%5,%6,%7}, {%8,%9}, {%0,%1,%2,%3};"
        : "+f"(d.x), "+f"(d.y), "+f"(d.z), "+f"(d.w)
        : "r"(a.x), "r"(a.y), "r"(a.z), "r"(a.w), "r"(b0), "r"(b1));
}

// ---------------------------------------------------------------------------
__global__ void init_colmin_kernel() {
    int i = blockIdx.x * blockDim.x + threadIdx.x;
    if (i < MM) g_colmin[i] = 0x7f800000u;
}

// Pack e for the per-warp ring layout (see g_eB comment).
// Fragment (nf=2*nfp+h, ln) of chunk g=(j*16+kc), wx-slice:
//   n = wx*64 + nf*8 + (ln>>2), c = ln&3
//   uint2 = { bf16x2(e[n'][16kc+2c], [+1]), bf16x2(e[n'][16kc+2c+8], [+9]) }
__global__ void prep_eB_kernel(const float* __restrict__ e) {
    int gid = blockIdx.x * blockDim.x + threadIdx.x;
    if (gid >= MM * DD / 4) return;
    int h   = gid & 1;
    int ln  = (gid >> 1) & 31;
    int nfp = (gid >> 6) & 3;
    int wx  = (gid >> 8) & 3;
    int g   = gid >> 10;
    int kc  = g & 15;
    int j   = g >> 4;
    int nf  = nfp * 2 + h;
    int n   = wx * 64 + nf * 8 + (ln >> 2);
    int c   = ln & 3;
    const float* row = e + (size_t)(j * 256 + n) * DD + kc * 16;
    uint2 v;
    v.x = bf2(row[2 * c],     row[2 * c + 1]);
    v.y = bf2(row[2 * c + 8], row[2 * c + 9]);
    g_eB[gid] = v;
}

__global__ void esq_kernel(const float* __restrict__ e) {
    int warp = (blockIdx.x * blockDim.x + threadIdx.x) >> 5;
    int lane = threadIdx.x & 31;
    if (warp >= MM) return;
    const float* row = e + (size_t)warp * DD;
    float s = 0.f;
    #pragma unroll
    for (int i = 0; i < DD / 32; i++) { float v = row[lane + i * 32]; s += v * v; }
    #pragma unroll
    for (int o = 16; o > 0; o >>= 1) s += __shfl_down_sync(0xffffffffu, s, o);
    if (lane == 0) g_esq[warp] = s;
}

// ---------------------------------------------------------------------------
// Fused GEMM + distance + column-min. 256 CTAs x 256 threads (2 CTAs/SM).
// Warp tile 32x64. Per-warp cp.async ring for B; no mainloop block barriers.
__global__ void __launch_bounds__(256, 2)
gemm_dist_kernel(const float* __restrict__ z, float* __restrict__ out) {
    extern __shared__ char smem[];
    uint4* Ash   = (uint4*)(smem + SM_A);
    float* zpart = (float*)(smem + SM_ZPART);
    float* zrow  = (float*)(smem + SM_ZROW);

    const int tid = threadIdx.x;
    const int wid = tid >> 5;
    const int lane = tid & 31;
    const int wy = wid & 1;          // rows wy*32..+31
    const int wx = wid >> 1;         // cols wx*64..+63 (within 256-wide chunk)
    const int n0 = blockIdx.x << 6;  // 64-row tile
    const float* zbase = z + (size_t)(n0 >> 10) * (DD * 1024) + (n0 & 1023);

    // per-warp B ring: 4 stages x 2KB
    const uint32_t sbBw = smem_u32(smem + SM_B) + (uint32_t)wid * 8192
                        + (uint32_t)lane * 16;
    const char* srcB = (const char*)g_eB + (size_t)(wx * 2048 + lane * 16);

    auto issueB = [&](int g) {
        uint32_t dst = sbBw + (uint32_t)(g & 3) * 2048;
        const char* s = srcB + (size_t)g * 8192;
        CP_ASYNC16(dst,        s);
        CP_ASYNC16(dst + 512,  s + 512);
        CP_ASYNC16(dst + 1024, s + 1024);
        CP_ASYNC16(dst + 1536, s + 1536);
        CP_COMMIT();
    };
    issueB(0); issueB(1); issueB(2);

    // ---- prologue 1: z_sq partials ----
    {
        float zacc = 0.f;
        const int an = tid & 63;
        const int dh = tid >> 6;
        #pragma unroll 8
        for (int it = 0; it < 64; it++) {
            float v = zbase[(size_t)(dh * 64 + it) * 1024 + an];
            zacc += v * v;
        }
        zpart[tid] = zacc;
    }
    __syncthreads();
    if (tid < 64)
        zrow[tid] = zpart[tid] + zpart[tid + 64] + zpart[tid + 128] + zpart[tid + 192];

    // ---- prologue 2: build A' fragment-major (m16n8k16 bf16 A layout) ----
    #pragma unroll 4
    for (int it = 0; it < 8; it++) {
        int f = it * 256 + tid;
        int ln = f & 31, kstep = (f >> 5) & 15, rbg = f >> 9;
        int rr = rbg * 16 + (ln >> 2);
        int d0 = kstep * 16 + (ln & 3) * 2;
        float z00 = __ldg(zbase + (size_t)d0 * 1024 + rr);
        float z01 = __ldg(zbase + (size_t)(d0 + 1) * 1024 + rr);
        float z10 = __ldg(zbase + (size_t)d0 * 1024 + rr + 8);
        float z11 = __ldg(zbase + (size_t)(d0 + 1) * 1024 + rr + 8);
        float z02 = __ldg(zbase + (size_t)(d0 + 8) * 1024 + rr);
        float z03 = __ldg(zbase + (size_t)(d0 + 9) * 1024 + rr);
        float z12 = __ldg(zbase + (size_t)(d0 + 8) * 1024 + rr + 8);
        float z13 = __ldg(zbase + (size_t)(d0 + 9) * 1024 + rr + 8);
        uint4 a;
        a.x = bf2(z00, z01);
        a.y = bf2(z10, z11);
        a.z = bf2(z02, z03);
        a.w = bf2(z12, z13);
        Ash[(rbg * 16 + kstep) * 32 + ln] = a;
    }
    __syncthreads();   // A', zrow ready — LAST block barrier

    // ---- accumulators: warp tile 32 x 64 (2 rowblocks x 8 n-frags) ----
    float4 acc[2][8];
    #pragma unroll
    for (int i = 0; i < 2; i++)
        #pragma unroll
        for (int nf = 0; nf < 8; nf++) acc[i][nf] = make_float4(0.f, 0.f, 0.f, 0.f);

    const int a_base = (wy * 2) * 512 + lane;          // rbg = wy*2 + i, stride 512
    const int r_lo = (lane >> 2);
    const uint4* Bring = (const uint4*)(smem + SM_B + wid * 8192) + lane;

    for (int v = 0; v < 128; v++) {
        const int kc = v & 15, st = v & 3;
        if (v < 126)      { CP_WAIT(2); }
        else if (v == 126){ CP_WAIT(1); }
        else              { CP_WAIT(0); }

        // B: 4 conflict-free LDS.128 (pairs of fragments)
        uint4 bq[4];
        #pragma unroll
        for (int nfp = 0; nfp < 4; nfp++)
            bq[nfp] = Bring[st * 128 + nfp * 32];
        // A: 2 conflict-free LDS.128
        uint4 af[2];
        #pragma unroll
        for (int i = 0; i < 2; i++)
            af[i] = Ash[a_base + i * 512 + kc * 32];

        #pragma unroll
        for (int i = 0; i < 2; i++)
            #pragma unroll
            for (int nfp = 0; nfp < 4; nfp++) {
                mma_bf16(acc[i][nfp * 2],     af[i], bq[nfp].x, bq[nfp].y);
                mma_bf16(acc[i][nfp * 2 + 1], af[i], bq[nfp].z, bq[nfp].w);
            }

        if (v + 3 < 128) issueB(v + 3);

        if (kc == 15) {
            // ------- register-direct epilogue for m-chunk j (256 wide) -------
            const int j = v >> 4;
            float mn[8][2];
            #pragma unroll
            for (int i = 0; i < 2; i++) {
                const float zr0 = zrow[wy * 32 + i * 16 + r_lo];
                const float zr1 = zrow[wy * 32 + i * 16 + r_lo + 8];
                float* orow0 = out + (size_t)(n0 + wy * 32 + i * 16 + r_lo) * MM + j * 256;
                float* orow1 = orow0 + (size_t)8 * MM;
                #pragma unroll
                for (int nf = 0; nf < 8; nf++) {
                    const int col = wx * 64 + nf * 8 + (lane & 3) * 2;
                    float2 ev = *(const float2*)(g_esq + j * 256 + col);
                    float4 a = acc[i][nf];
                    float d00 = fmaxf(fmaf(-2.f, a.x, zr0 + ev.x), 0.f);
                    float d01 = fmaxf(fmaf(-2.f, a.y, zr0 + ev.y), 0.f);
                    float d10 = fmaxf(fmaf(-2.f, a.z, zr1 + ev.x), 0.f);
                    float d11 = fmaxf(fmaf(-2.f, a.w, zr1 + ev.y), 0.f);
                    *(float2*)(orow0 + col) = make_float2(d00, d01);
                    *(float2*)(orow1 + col) = make_float2(d10, d11);
                    float m0 = fminf(d00, d10), m1 = fminf(d01, d11);
                    if (i == 0) { mn[nf][0] = m0; mn[nf][1] = m1; }
                    else        { mn[nf][0] = fminf(mn[nf][0], m0);
                                  mn[nf][1] = fminf(mn[nf][1], m1); }
                    acc[i][nf] = make_float4(0.f, 0.f, 0.f, 0.f);
                }
            }
            #pragma unroll
            for (int nf = 0; nf < 8; nf++) {
                #pragma unroll
                for (int h = 0; h < 2; h++) {
                    float m = mn[nf][h];
                    m = fminf(m, __shfl_xor_sync(0xffffffffu, m, 4));
                    m = fminf(m, __shfl_xor_sync(0xffffffffu, m, 8));
                    m = fminf(m, __shfl_xor_sync(0xffffffffu, m, 16));
                    mn[nf][h] = m;
                }
            }
            if (r_lo == 0) {
                #pragma unroll
                for (int nf = 0; nf < 8; nf++) {
                    const int col = j * 256 + wx * 64 + nf * 8 + (lane & 3) * 2;
                    RED_MIN_U32(&g_colmin[col],     __float_as_uint(mn[nf][0]));
                    RED_MIN_U32(&g_colmin[col + 1], __float_as_uint(mn[nf][1]));
                }
            }
        }
    }
}

// ---------------------------------------------------------------------------
__global__ void loss_kernel(float* __restrict__ out_loss) {
    __shared__ float partial[256];
    int tid = threadIdx.x;
    float s = 0.f;
    for (int i = tid; i < MM; i += 256) s += __uint_as_float(g_colmin[i]);
    partial[tid] = s;
    __syncthreads();
    for (int o = 128; o > 0; o >>= 1) {
        if (tid < o) partial[tid] += partial[tid + o];
        __syncthreads();
    }
    if (tid == 0) out_loss[0] = partial[0] / (float)MM;
}

// ---------------------------------------------------------------------------
extern "C" void kernel_launch(void* const* d_in, const int* in_sizes, int n_in,
                              void* d_out, int out_size) {
    const float* z = (const float*)d_in[0];
    const float* e = (const float*)d_in[1];
    float* out = (float*)d_out;

    cudaFuncSetAttribute(gemm_dist_kernel,
                         cudaFuncAttributeMaxDynamicSharedMemorySize, SMEM_TOTAL);

    init_colmin_kernel<<<(MM + 255) / 256, 256>>>();
    prep_eB_kernel<<<(MM * DD / 4 + 255) / 256, 256>>>(e);
    esq_kernel<<<(MM * 32 + 255) / 256, 256>>>(e);

    gemm_dist_kernel<<<256, 256, SMEM_TOTAL>>>(z, out);

    loss_kernel<<<1, 256>>>(out + (size_t)NN * MM);
}

// round 17
// speedup vs baseline: 1.0684x; 1.0684x over previous
#include <cuda_runtime.h>
#include <cuda_bf16.h>
#include <cstdint>

#define NN 16384
#define MM 2048
#define DD 256

// 64-row n-tiles, 256 CTAs x 512 threads, 2 CTAs/SM (32 warps/SM).
// Warp tile 32x32. B from L2 via reg double-buffer; no mainloop barriers.
// dynamic SMEM layout (bytes)
#define SM_A     0                 // A': 2048 uint4 (bf16) = 32768
#define SM_ZPART 32768             // 512 f32
#define SM_ZROW  34816             // 64 f32
#define SMEM_TOTAL 35072

__device__ __align__(16) uint2 g_eB[DD * MM / 4];  // fragment-packed bf16 B (1MB)
__device__ float    g_esq[MM];
__device__ unsigned g_colmin[MM];

// ---------------------------------------------------------------------------
__device__ __forceinline__ uint32_t bf2(float lo, float hi) {
    uint32_t r;
    asm("cvt.rn.bf16x2.f32 %0, %1, %2;" : "=r"(r) : "f"(hi), "f"(lo));
    return r;
}
#define RED_MIN_U32(ptr, val) \
    asm volatile("red.global.min.u32 [%0], %1;" :: "l"(ptr), "r"(val) : "memory")

__device__ __forceinline__ void mma_bf16(float4& d, const uint4& a, uint32_t b0, uint32_t b1) {
    asm volatile("mma.sync.aligned.m16n8k16.row.col.f32.bf16.bf16.f32 "
        "{%0,%1,%2,%3}, {%4,%5,%6,%7}, {%8,%9}, {%0,%1,%2,%3};"
        : "+f"(d.x), "+f"(d.y), "+f"(d.z), "+f"(d.w)
        : "r"(a.x), "r"(a.y), "r"(a.z), "r"(a.w), "r"(b0), "r"(b1));
}

// ---------------------------------------------------------------------------
__global__ void init_colmin_kernel() {
    int i = blockIdx.x * blockDim.x + threadIdx.x;
    if (i < MM) g_colmin[i] = 0x7f800000u;
}

// Pack e fragment-major for mma.m16n8k16.bf16 B operand, m-chunks of 256:
// uint2 at ((j*16+kc)*256 + n)*4 + c = { bf16x2(e[j*256+n][16kc+2c], [+1]),
//                                        bf16x2(e[j*256+n][16kc+2c+8], [+9]) }
__global__ void prep_eB_kernel(const float* __restrict__ e) {
    int gid = blockIdx.x * blockDim.x + threadIdx.x;
    if (gid >= MM * DD / 4) return;
    int c  = gid & 3;
    int n  = (gid >> 2) & 255;
    int kc = (gid >> 10) & 15;
    int j  = gid >> 14;
    const float* row = e + (size_t)(j * 256 + n) * DD + kc * 16;
    uint2 v;
    v.x = bf2(row[2 * c],     row[2 * c + 1]);
    v.y = bf2(row[2 * c + 8], row[2 * c + 9]);
    g_eB[gid] = v;
}

__global__ void esq_kernel(const float* __restrict__ e) {
    int warp = (blockIdx.x * blockDim.x + threadIdx.x) >> 5;
    int lane = threadIdx.x & 31;
    if (warp >= MM) return;
    const float* row = e + (size_t)warp * DD;
    float s = 0.f;
    #pragma unroll
    for (int i = 0; i < DD / 32; i++) { float v = row[lane + i * 32]; s += v * v; }
    #pragma unroll
    for (int o = 16; o > 0; o >>= 1) s += __shfl_down_sync(0xffffffffu, s, o);
    if (lane == 0) g_esq[warp] = s;
}

// ---------------------------------------------------------------------------
// Fused GEMM + distance + column-min. 256 CTAs x 512 threads (2 CTAs/SM).
// Warp tile 32x32 (16 warps: 2 wy x 8 wx). Reg-double-buffered B from L2.
__global__ void __launch_bounds__(512, 2)
gemm_dist_kernel(const float* __restrict__ z, float* __restrict__ out) {
    extern __shared__ char smem[];
    uint4* Ash   = (uint4*)(smem + SM_A);
    float* zpart = (float*)(smem + SM_ZPART);
    float* zrow  = (float*)(smem + SM_ZROW);

    const int tid = threadIdx.x;
    const int wid = tid >> 5;
    const int lane = tid & 31;
    const int wy = wid & 1;          // rows wy*32..+31
    const int wx = wid >> 1;         // cols wx*32..+31 (within 256-wide chunk)
    const int n0 = blockIdx.x << 6;  // 64-row tile
    const float* zbase = z + (size_t)(n0 >> 10) * (DD * 1024) + (n0 & 1023);

    // ---- prologue 1: z_sq partials ----
    {
        float zacc = 0.f;
        const int an = tid & 63;
        const int dh = tid >> 6;          // 0..7, 32 d's each
        #pragma unroll 8
        for (int it = 0; it < 32; it++) {
            float v = zbase[(size_t)(dh * 32 + it) * 1024 + an];
            zacc += v * v;
        }
        zpart[tid] = zacc;
    }
    __syncthreads();
    if (tid < 64) {
        float s = 0.f;
        #pragma unroll
        for (int p = 0; p < 8; p++) s += zpart[tid + p * 64];
        zrow[tid] = s;
    }

    // ---- prologue 2: build A' fragment-major (m16n8k16 bf16 A layout) ----
    #pragma unroll 4
    for (int it = 0; it < 4; it++) {
        int f = it * 512 + tid;
        int ln = f & 31, kstep = (f >> 5) & 15, rbg = f >> 9;
        int rr = rbg * 16 + (ln >> 2);
        int d0 = kstep * 16 + (ln & 3) * 2;
        float z00 = __ldg(zbase + (size_t)d0 * 1024 + rr);
        float z01 = __ldg(zbase + (size_t)(d0 + 1) * 1024 + rr);
        float z10 = __ldg(zbase + (size_t)d0 * 1024 + rr + 8);
        float z11 = __ldg(zbase + (size_t)(d0 + 1) * 1024 + rr + 8);
        float z02 = __ldg(zbase + (size_t)(d0 + 8) * 1024 + rr);
        float z03 = __ldg(zbase + (size_t)(d0 + 9) * 1024 + rr);
        float z12 = __ldg(zbase + (size_t)(d0 + 8) * 1024 + rr + 8);
        float z13 = __ldg(zbase + (size_t)(d0 + 9) * 1024 + rr + 8);
        uint4 a;
        a.x = bf2(z00, z01);
        a.y = bf2(z10, z11);
        a.z = bf2(z02, z03);
        a.w = bf2(z12, z13);
        Ash[(rbg * 16 + kstep) * 32 + ln] = a;
    }
    __syncthreads();   // A', zrow ready — LAST block barrier

    // ---- accumulators: warp tile 32 x 32 (2 rowblocks x 4 n-frags) ----
    float4 acc[2][4];
    #pragma unroll
    for (int i = 0; i < 2; i++)
        #pragma unroll
        for (int nf = 0; nf < 4; nf++) acc[i][nf] = make_float4(0.f, 0.f, 0.f, 0.f);

    const int a_base = (wy * 2) * 512 + lane;          // rbg = wy*2 + i, stride 512
    const int r_lo = (lane >> 2);
    const uint2* gB = g_eB + (wx * 32 + (lane >> 2)) * 4 + (lane & 3);

    // B register double buffer (chunk granularity: k16, 4 frags = 8 regs each)
    uint2 bufA[4], bufB[4];
    #pragma unroll
    for (int nf = 0; nf < 4; nf++) bufA[nf] = __ldg(gB + nf * 32);

    // 128 k16-chunks (8 m-chunks x 16 k-chunks); unroll by 2 for static bufs
    for (int v = 0; v < 64; v++) {
        const int g0 = 2 * v;
        // prefetch g0+1 into bufB
        {
            const uint2* p = gB + (size_t)(g0 + 1) * 1024;
            #pragma unroll
            for (int nf = 0; nf < 4; nf++) bufB[nf] = __ldg(p + nf * 32);
        }
        // compute chunk g0 from bufA
        {
            const int kc = g0 & 15;
            uint4 af[2];
            #pragma unroll
            for (int i = 0; i < 2; i++) af[i] = Ash[a_base + i * 512 + kc * 32];
            #pragma unroll
            for (int i = 0; i < 2; i++)
                #pragma unroll
                for (int nf = 0; nf < 4; nf++)
                    mma_bf16(acc[i][nf], af[i], bufA[nf].x, bufA[nf].y);
        }
        // prefetch g0+2 into bufA
        if (v < 63) {
            const uint2* p = gB + (size_t)(g0 + 2) * 1024;
            #pragma unroll
            for (int nf = 0; nf < 4; nf++) bufA[nf] = __ldg(p + nf * 32);
        }
        // compute chunk g0+1 from bufB
        {
            const int kc = (g0 + 1) & 15;
            uint4 af[2];
            #pragma unroll
            for (int i = 0; i < 2; i++) af[i] = Ash[a_base + i * 512 + kc * 32];
            #pragma unroll
            for (int i = 0; i < 2; i++)
                #pragma unroll
                for (int nf = 0; nf < 4; nf++)
                    mma_bf16(acc[i][nf], af[i], bufB[nf].x, bufB[nf].y);
        }

        if ((v & 7) == 7) {
            // ------- register-direct epilogue for m-chunk j (256 wide) -------
            const int j = v >> 3;
            float mn[4][2];
            #pragma unroll
            for (int i = 0; i < 2; i++) {
                const float zr0 = zrow[wy * 32 + i * 16 + r_lo];
                const float zr1 = zrow[wy * 32 + i * 16 + r_lo + 8];
                float* orow0 = out + (size_t)(n0 + wy * 32 + i * 16 + r_lo) * MM + j * 256;
                float* orow1 = orow0 + (size_t)8 * MM;
                #pragma unroll
                for (int nf = 0; nf < 4; nf++) {
                    const int col = wx * 32 + nf * 8 + (lane & 3) * 2;
                    float2 ev = *(const float2*)(g_esq + j * 256 + col);
                    float4 a = acc[i][nf];
                    float d00 = fmaxf(fmaf(-2.f, a.x, zr0 + ev.x), 0.f);
                    float d01 = fmaxf(fmaf(-2.f, a.y, zr0 + ev.y), 0.f);
                    float d10 = fmaxf(fmaf(-2.f, a.z, zr1 + ev.x), 0.f);
                    float d11 = fmaxf(fmaf(-2.f, a.w, zr1 + ev.y), 0.f);
                    *(float2*)(orow0 + col) = make_float2(d00, d01);
                    *(float2*)(orow1 + col) = make_float2(d10, d11);
                    float m0 = fminf(d00, d10), m1 = fminf(d01, d11);
                    if (i == 0) { mn[nf][0] = m0; mn[nf][1] = m1; }
                    else        { mn[nf][0] = fminf(mn[nf][0], m0);
                                  mn[nf][1] = fminf(mn[nf][1], m1); }
                    acc[i][nf] = make_float4(0.f, 0.f, 0.f, 0.f);
                }
            }
            #pragma unroll
            for (int nf = 0; nf < 4; nf++) {
                #pragma unroll
                for (int h = 0; h < 2; h++) {
                    float m = mn[nf][h];
                    m = fminf(m, __shfl_xor_sync(0xffffffffu, m, 4));
                    m = fminf(m, __shfl_xor_sync(0xffffffffu, m, 8));
                    m = fminf(m, __shfl_xor_sync(0xffffffffu, m, 16));
                    mn[nf][h] = m;
                }
            }
            if (r_lo == 0) {
                #pragma unroll
                for (int nf = 0; nf < 4; nf++) {
                    const int col = j * 256 + wx * 32 + nf * 8 + (lane & 3) * 2;
                    RED_MIN_U32(&g_colmin[col],     __float_as_uint(mn[nf][0]));
                    RED_MIN_U32(&g_colmin[col + 1], __float_as_uint(mn[nf][1]));
                }
            }
        }
    }
}

// ---------------------------------------------------------------------------
__global__ void loss_kernel(float* __restrict__ out_loss) {
    __shared__ float partial[256];
    int tid = threadIdx.x;
    float s = 0.f;
    for (int i = tid; i < MM; i += 256) s += __uint_as_float(g_colmin[i]);
    partial[tid] = s;
    __syncthreads();
    for (int o = 128; o > 0; o >>= 1) {
        if (tid < o) partial[tid] += partial[tid + o];
        __syncthreads();
    }
    if (tid == 0) out_loss[0] = partial[0] / (float)MM;
}

// ---------------------------------------------------------------------------
extern "C" void kernel_launch(void* const* d_in, const int* in_sizes, int n_in,
                              void* d_out, int out_size) {
    const float* z = (const float*)d_in[0];
    const float* e = (const float*)d_in[1];
    float* out = (float*)d_out;

    cudaFuncSetAttribute(gemm_dist_kernel,
                         cudaFuncAttributeMaxDynamicSharedMemorySize, SMEM_TOTAL);

    init_colmin_kernel<<<(MM + 255) / 256, 256>>>();
    prep_eB_kernel<<<(MM * DD / 4 + 255) / 256, 256>>>(e);
    esq_kernel<<<(MM * 32 + 255) / 256, 256>>>(e);

    gemm_dist_kernel<<<256, 512, SMEM_TOTAL>>>(z, out);

    loss_kernel<<<1, 256>>>(out + (size_t)NN * MM);
}